// round 5
// baseline (speedup 1.0000x reference)
#include <cuda_runtime.h>
#include <cstdint>

// Problem constants
// B=4, C=64, H=W=64, PS=4, PD=1, UFSTRIDE=2, STRIDE=1, SCALE=10
// L = 32*32 = 1024 kernels, hs=ws=63, P = 3969
// GEMM per batch: M=L=1024, N=P=3969 (padded 4096), K=C*16=1024

#define NB    4
#define NC    64
#define HW    64
#define LL    1024        // number of kernels (M)
#define KK    1024        // reduction dim
#define PP    3969        // hs*ws
#define PPAD  4096        // padded N for unguarded loads
#define CSTR  3972        // padded row stride for cos/tmp (16B aligned rows)

static __device__ float d_invn[NB * NC];
static __device__ float d_A   [(size_t)NB * KK * LL];     // [b][k][l]  (k-major)
static __device__ float d_Fcol[(size_t)NB * KK * PPAD];   // [b][k][p]
static __device__ float d_cos [(size_t)NB * LL * CSTR];   // gemm out, later cosF (masked fused cos)
static __device__ float d_tmp [(size_t)NB * LL * CSTR];   // pass1 out
static __device__ float d_mmk [NB * LL];
static __device__ float d_mmp [NB * PP];
static __device__ float d_maxv[NB * PP];
static __device__ float d_rcps[NB * PP];

__device__ __forceinline__ int clamp64(int v) { return min(max(v, 0), 63); }

// ---------------------------------------------------------------------------
// 1) per-(b,c) inverse L2 norm of b
// ---------------------------------------------------------------------------
__global__ void norm_kernel(const float* __restrict__ bsrc) {
    int bc = blockIdx.x;                     // 0..255
    const float* src = bsrc + (size_t)bc * 4096;
    float s = 0.f;
    for (int i = threadIdx.x; i < 4096; i += 256) {
        float v = src[i];
        s += v * v;
    }
    __shared__ float sh[256];
    sh[threadIdx.x] = s;
    __syncthreads();
    for (int o = 128; o > 0; o >>= 1) {
        if (threadIdx.x < o) sh[threadIdx.x] += sh[threadIdx.x + o];
        __syncthreads();
    }
    if (threadIdx.x == 0) d_invn[bc] = 1.0f / sqrtf(sh[0] + 1e-8f);
}

// ---------------------------------------------------------------------------
// 2) build A_T[b][k][l] = bn patch kernels (k = c*16 + i*4 + j, l = ly*32+lx)
// ---------------------------------------------------------------------------
__global__ void build_A_kernel(const float* __restrict__ bsrc) {
    int idx = blockIdx.x * 256 + threadIdx.x;       // 4*1024*1024 total
    int l  = idx & 1023;
    int k  = (idx >> 10) & 1023;
    int bI = idx >> 20;
    int c  = k >> 4;
    int i  = (k >> 2) & 3;
    int j  = k & 3;
    int ly = l >> 5, lx = l & 31;
    int h = clamp64(2 * ly + i - 1);
    int w = clamp64(2 * lx + j - 1);
    float v = bsrc[((size_t)(bI * NC + c)) * 4096 + h * 64 + w] * d_invn[bI * NC + c];
    d_A[idx] = v;
}

// ---------------------------------------------------------------------------
// 3) build Fcol[b][k][p] = im2col of padded f (p = y*63+x), zero beyond PP
// ---------------------------------------------------------------------------
__global__ void build_F_kernel(const float* __restrict__ fsrc) {
    size_t idx = (size_t)blockIdx.x * 256 + threadIdx.x;  // 4*1024*4096 total
    int p  = (int)(idx & 4095);
    int k  = (int)((idx >> 12) & 1023);
    int bI = (int)(idx >> 22);
    float v = 0.f;
    if (p < PP) {
        int y = p / 63;
        int x = p - 63 * y;
        int c = k >> 4;
        int i = (k >> 2) & 3;
        int j = k & 3;
        int h = clamp64(y + i - 1);
        int w = clamp64(x + j - 1);
        v = fsrc[((size_t)(bI * NC + c)) * 4096 + h * 64 + w];
    }
    d_Fcol[idx] = v;
}

// ---------------------------------------------------------------------------
// 4) mmk[b][l] : mean of 4x4 patch of (1-mask) on stride-2 grid (exact n/16)
// ---------------------------------------------------------------------------
__global__ void mmk_kernel(const float* __restrict__ mask) {
    int idx = blockIdx.x * 256 + threadIdx.x;   // 4096 total
    int l = idx & 1023, b = idx >> 10;
    int ly = l >> 5, lx = l & 31;
    const float* m = mask + (size_t)b * 4096;
    float s = 0.f;
    #pragma unroll
    for (int i = 0; i < 4; i++)
        #pragma unroll
        for (int j = 0; j < 4; j++) {
            int h = clamp64(2 * ly + i - 1);
            int w = clamp64(2 * lx + j - 1);
            s += 1.0f - m[h * 64 + w];
        }
    d_mmk[idx] = s * 0.0625f;
}

// ---------------------------------------------------------------------------
// 5) mmp[b][p] : mean of 4x4 patch of (1-mask) on stride-1 grid
// ---------------------------------------------------------------------------
__global__ void mmp_kernel(const float* __restrict__ mask) {
    int p = blockIdx.x * 256 + threadIdx.x;
    if (p >= PP) return;
    int b = blockIdx.y;
    int y = p / 63, x = p - 63 * y;
    const float* m = mask + (size_t)b * 4096;
    float s = 0.f;
    #pragma unroll
    for (int i = 0; i < 4; i++)
        #pragma unroll
        for (int j = 0; j < 4; j++) {
            int h = clamp64(y + i - 1);
            int w = clamp64(x + j - 1);
            s += 1.0f - m[h * 64 + w];
        }
    d_mmp[b * PP + p] = s * 0.0625f;
}

// ---------------------------------------------------------------------------
// 6) GEMM: cos[b][l][p] = sum_k A[b][k][l] * Fcol[b][k][p]
//    128x128x16 tiles, 256 threads, 8x8 per thread, fp32 via packed fma.rn.f32x2
// ---------------------------------------------------------------------------
#define BM 128
#define BN 128
#define BKD 16

__global__ void __launch_bounds__(256, 2)
gemm_kernel() {
    int bI = blockIdx.z;
    int m0 = blockIdx.y * BM;
    int n0 = blockIdx.x * BN;
    const float* __restrict__ Ab = d_A    + (size_t)bI * KK * LL;
    const float* __restrict__ Bb = d_Fcol + (size_t)bI * KK * PPAD;

    __shared__ __align__(16) float As[BKD][BM];
    __shared__ __align__(16) float Bs[BKD][BN];

    int tid = threadIdx.x;
    int tn = tid & 15;          // 0..15 -> n sub-block of 8
    int tm = tid >> 4;          // 0..15 -> m sub-block of 8
    int ka = tid >> 5;          // 0..7  loader k row
    int ma = (tid & 31) * 4;    // 0..124 loader col (float4)

    unsigned long long acc[8][4];
    #pragma unroll
    for (int i = 0; i < 8; i++)
        #pragma unroll
        for (int j = 0; j < 4; j++) acc[i][j] = 0ull;

    for (int k0 = 0; k0 < KK; k0 += BKD) {
        *(float4*)&As[ka][ma]     = *(const float4*)&Ab[(size_t)(k0 + ka) * LL + m0 + ma];
        *(float4*)&As[ka + 8][ma] = *(const float4*)&Ab[(size_t)(k0 + ka + 8) * LL + m0 + ma];
        *(float4*)&Bs[ka][ma]     = *(const float4*)&Bb[(size_t)(k0 + ka) * PPAD + n0 + ma];
        *(float4*)&Bs[ka + 8][ma] = *(const float4*)&Bb[(size_t)(k0 + ka + 8) * PPAD + n0 + ma];
        __syncthreads();
        #pragma unroll
        for (int k = 0; k < BKD; k++) {
            float4 a0 = *(const float4*)&As[k][tm * 8];
            float4 a1 = *(const float4*)&As[k][tm * 8 + 4];
            ulonglong2 bv0 = *(const ulonglong2*)&Bs[k][tn * 8];
            ulonglong2 bv1 = *(const ulonglong2*)&Bs[k][tn * 8 + 4];
            unsigned long long bq[4] = {bv0.x, bv0.y, bv1.x, bv1.y};
            float av[8] = {a0.x, a0.y, a0.z, a0.w, a1.x, a1.y, a1.z, a1.w};
            unsigned long long ap[8];
            #pragma unroll
            for (int i = 0; i < 8; i++)
                asm("mov.b64 %0, {%1, %1};" : "=l"(ap[i]) : "r"(__float_as_uint(av[i])));
            #pragma unroll
            for (int i = 0; i < 8; i++)
                #pragma unroll
                for (int j = 0; j < 4; j++)
                    asm("fma.rn.f32x2 %0, %1, %2, %0;"
                        : "+l"(acc[i][j]) : "l"(ap[i]), "l"(bq[j]));
        }
        __syncthreads();
    }

    // store (guard n < PP)
    #pragma unroll
    for (int i = 0; i < 8; i++) {
        int m = m0 + tm * 8 + i;
        float* Crow = d_cos + ((size_t)(bI * LL + m)) * CSTR;
        #pragma unroll
        for (int j = 0; j < 4; j++) {
            unsigned int ulo, uhi;
            asm("mov.b64 {%0, %1}, %2;" : "=r"(ulo), "=r"(uhi) : "l"(acc[i][j]));
            int n = n0 + tn * 8 + 2 * j;
            if (n < PP)     Crow[n]     = __uint_as_float(ulo);
            if (n + 1 < PP) Crow[n + 1] = __uint_as_float(uhi);
        }
    }
}

// ---------------------------------------------------------------------------
// 7) pass1: diag3 on flat (1024, 3969) matrix (zero-pad at flat borders)
// ---------------------------------------------------------------------------
__global__ void pass1_kernel() {
    int q = blockIdx.x * 256 + threadIdx.x;
    if (q >= PP) return;
    int br = blockIdx.y;                       // b*1024 + r
    const float* base = d_cos + (size_t)(br >> 10) * LL * CSTR;
    int r = br & 1023;
    float s = base[(size_t)r * CSTR + q];
    if (r > 0 && q > 0)        s += base[(size_t)(r - 1) * CSTR + q - 1];
    if (r < 1023 && q < PP - 1) s += base[(size_t)(r + 1) * CSTR + q + 1];
    d_tmp[(size_t)br * CSTR + q] = s;
}

// ---------------------------------------------------------------------------
// 8) pass2: diag3 on the transposed-index view, expressed in original layout,
//    plus mask multiply. Writes masked fused cos back into d_cos.
// ---------------------------------------------------------------------------
__global__ void pass2_kernel() {
    int q = blockIdx.x * 256 + threadIdx.x;
    if (q >= PP) return;
    int br = blockIdx.y;
    int b = br >> 10;
    int r = br & 1023;
    int ly = r >> 5, lx = r & 31;
    int r2 = lx * 32 + ly;
    int y = q / 63, x = q - 63 * y;
    int q2 = x * 63 + y;
    const float* tb = d_tmp + (size_t)b * LL * CSTR;
    float s = 0.f;
    #pragma unroll
    for (int d = -1; d <= 1; d++) {
        int rr = r2 + d, qq = q2 + d;
        if (rr >= 0 && rr < 1024 && qq >= 0 && qq < PP) {
            int lx2 = rr >> 5, ly2 = rr & 31;
            int x2 = qq / 63, y2 = qq - 63 * x2;
            s += tb[(size_t)(ly2 * 32 + lx2) * CSTR + (y2 * 63 + x2)];
        }
    }
    float mk = d_mmk[b * LL + r];
    float mp = d_mmp[b * PP + q];
    float mm = ((mk > mp && mp > 0.5f) || (mk == 1.0f)) ? 1.0f : 0.0f;
    d_cos[(size_t)br * CSTR + q] = s * mm;
}

// ---------------------------------------------------------------------------
// 9) softmax reduce over l (online max/sum), 32 p-lanes x 8 l-strides per block
// ---------------------------------------------------------------------------
__global__ void smax_reduce_kernel() {
    int b  = blockIdx.y;
    int pl = threadIdx.x & 31;
    int lt = threadIdx.x >> 5;
    int p  = blockIdx.x * 32 + pl;
    float m = -1e30f, s = 0.f;
    if (p < PP) {
        const float* cf = d_cos + (size_t)b * LL * CSTR + p;
        for (int l = lt; l < LL; l += 8) {
            float x = 10.0f * cf[(size_t)l * CSTR];
            float mn = fmaxf(m, x);
            s = s * __expf(m - mn) + __expf(x - mn);
            m = mn;
        }
    }
    __shared__ float shm[8][32], shs[8][32];
    shm[lt][pl] = m;
    shs[lt][pl] = s;
    __syncthreads();
    if (lt == 0 && p < PP) {
        float M = shm[0][pl];
        #pragma unroll
        for (int t = 1; t < 8; t++) M = fmaxf(M, shm[t][pl]);
        float S = 0.f;
        #pragma unroll
        for (int t = 0; t < 8; t++) S += shs[t][pl] * __expf(shm[t][pl] - M);
        d_maxv[b * PP + p] = M;
        d_rcps[b * PP + p] = 1.0f / S;
    }
}

// ---------------------------------------------------------------------------
// 10) softmax write: out[b][l][p] (exact 3969 stride, coalesced)
// ---------------------------------------------------------------------------
__global__ void smax_write_kernel(float* __restrict__ out) {
    int q = blockIdx.x * 256 + threadIdx.x;
    if (q >= PP) return;
    int bl = blockIdx.y;           // b*1024 + l
    int b = bl >> 10;
    float x = 10.0f * d_cos[(size_t)bl * CSTR + q];
    out[(size_t)bl * PP + q] = __expf(x - d_maxv[b * PP + q]) * d_rcps[b * PP + q];
}

// ---------------------------------------------------------------------------
extern "C" void kernel_launch(void* const* d_in, const int* in_sizes, int n_in,
                              void* d_out, int out_size) {
    const float* f    = (const float*)d_in[0];
    const float* bsrc = (const float*)d_in[1];
    const float* mask = (const float*)d_in[2];
    float* out = (float*)d_out;

    norm_kernel<<<NB * NC, 256>>>(bsrc);
    build_A_kernel<<<(NB * KK * LL) / 256, 256>>>(bsrc);
    build_F_kernel<<<(int)(((size_t)NB * KK * PPAD) / 256), 256>>>(f);
    mmk_kernel<<<(NB * LL) / 256, 256>>>(mask);
    mmp_kernel<<<dim3((PP + 255) / 256, NB), 256>>>(mask);

    gemm_kernel<<<dim3(PPAD / BN, LL / BM, NB), 256>>>();

    dim3 g2((PP + 255) / 256, NB * LL);
    pass1_kernel<<<g2, 256>>>();
    pass2_kernel<<<g2, 256>>>();

    smax_reduce_kernel<<<dim3((PP + 31) / 32, NB), 256>>>();
    smax_write_kernel<<<g2, 256>>>(out);
}

// round 7
// speedup vs baseline: 1.5798x; 1.5798x over previous
#include <cuda_runtime.h>
#include <cuda_bf16.h>
#include <cstdint>

// Problem constants
// B=4, C=64, H=W=64, PS=4, PD=1, UFSTRIDE=2, STRIDE=1, SCALE=10
// L = 1024 (M), hs=ws=63, P = 3969 (N, padded 4096), K = 1024 -> bf16 3-split K = 3072

#define NB    4
#define NC    64
#define LL    1024
#define KK    1024
#define GK    3072        // 3-split K
#define PP    3969
#define PPAD  4096
#define CSTR  3972

// GEMM tiling (HMMA mma.sync path — tcgen05 is ptxas-rejected on this harness's sm_103 target)
#define BM    128
#define BN    128
#define BKC   64                    // bf16 per K-chunk (128 B rows)
#define NCHUNK (GK / BKC)           // 48
#define ABYTES (BM * 128)           // 16384
#define BBYTES (BN * 128)           // 16384
#define BUFBYTES (ABYTES + BBYTES)  // 32768
#define SM_BYTES (2 * BUFBYTES)     // 65536

static __device__ float d_invn[NB * NC];
static __device__ __align__(16) __nv_bfloat16 d_Abf[(size_t)NB * LL * GK];    // [b][l][k']
static __device__ __align__(16) __nv_bfloat16 d_Fbf[(size_t)NB * PPAD * GK];  // [b][p][k']
static __device__ float d_cos [(size_t)NB * LL * CSTR];
static __device__ float d_tmp [(size_t)NB * LL * CSTR];
static __device__ float d_mmk [NB * LL];
static __device__ float d_mmp [NB * PP];
static __device__ float d_maxv[NB * PP];
static __device__ float d_rcps[NB * PP];

__device__ __forceinline__ int clamp64(int v) { return min(max(v, 0), 63); }

__device__ __forceinline__ uint32_t smem_u32(const void* p) {
    uint32_t a;
    asm("{ .reg .u64 t; cvta.to.shared.u64 t, %1; cvt.u32.u64 %0, t; }" : "=r"(a) : "l"(p));
    return a;
}
__device__ __forceinline__ void cp_async16(uint32_t dst, const void* src) {
    asm volatile("cp.async.cg.shared.global [%0], [%1], 16;" :: "r"(dst), "l"(src) : "memory");
}
__device__ __forceinline__ void ldsm_x4(uint32_t* r, uint32_t addr) {
    asm volatile("ldmatrix.sync.aligned.m8n8.x4.shared.b16 {%0,%1,%2,%3}, [%4];"
                 : "=r"(r[0]), "=r"(r[1]), "=r"(r[2]), "=r"(r[3]) : "r"(addr));
}
__device__ __forceinline__ void mma16816(float* c, const uint32_t* a, const uint32_t* b) {
    asm volatile(
        "mma.sync.aligned.m16n8k16.row.col.f32.bf16.bf16.f32 "
        "{%0,%1,%2,%3}, {%4,%5,%6,%7}, {%8,%9}, {%0,%1,%2,%3};"
        : "+f"(c[0]), "+f"(c[1]), "+f"(c[2]), "+f"(c[3])
        : "r"(a[0]), "r"(a[1]), "r"(a[2]), "r"(a[3]), "r"(b[0]), "r"(b[1]));
}
// swizzled smem offset: row r (128 B), 16-byte column c
__device__ __forceinline__ uint32_t swz(uint32_t base, int r, int c) {
    return base + r * 128 + ((c ^ (r & 7)) << 4);
}

// ---------------------------------------------------------------------------
// 1) per-(b,c) inverse L2 norm of b
// ---------------------------------------------------------------------------
__global__ void norm_kernel(const float* __restrict__ bsrc) {
    int bc = blockIdx.x;
    const float* src = bsrc + (size_t)bc * 4096;
    float s = 0.f;
    for (int i = threadIdx.x; i < 4096; i += 256) {
        float v = src[i];
        s += v * v;
    }
    __shared__ float sh[256];
    sh[threadIdx.x] = s;
    __syncthreads();
    for (int o = 128; o > 0; o >>= 1) {
        if (threadIdx.x < o) sh[threadIdx.x] += sh[threadIdx.x + o];
        __syncthreads();
    }
    if (threadIdx.x == 0) d_invn[bc] = 1.0f / sqrtf(sh[0] + 1e-8f);
}

// ---------------------------------------------------------------------------
// 2) bf16-split kernel matrix A[b][l][k'] segs [hi, hi, lo]
// ---------------------------------------------------------------------------
__global__ void build_A_bf3(const float* __restrict__ bsrc) {
    int idx = blockIdx.x * 256 + threadIdx.x;
    int k  = idx & 1023;
    int l  = (idx >> 10) & 1023;
    int bI = idx >> 20;
    int c  = k >> 4, i = (k >> 2) & 3, j = k & 3;
    int ly = l >> 5, lx = l & 31;
    int h = clamp64(2 * ly + i - 1);
    int w = clamp64(2 * lx + j - 1);
    float a = bsrc[((size_t)(bI * NC + c)) * 4096 + h * 64 + w] * d_invn[bI * NC + c];
    __nv_bfloat16 hi = __float2bfloat16(a);
    __nv_bfloat16 lo = __float2bfloat16(a - __bfloat162float(hi));
    size_t base = ((size_t)(bI * LL + l)) * GK;
    d_Abf[base + k]        = hi;
    d_Abf[base + 1024 + k] = hi;
    d_Abf[base + 2048 + k] = lo;
}

// ---------------------------------------------------------------------------
// 3) bf16-split im2col F[b][p][k'] segs [hi, lo, hi]
// ---------------------------------------------------------------------------
__global__ void build_F_bf3(const float* __restrict__ fsrc) {
    int idx = blockIdx.x * 256 + threadIdx.x;
    int k  = idx & 1023;
    int p  = (idx >> 10) & 4095;
    int bI = idx >> 22;
    float v = 0.f;
    if (p < PP) {
        int y = p / 63, x = p - 63 * y;
        int c = k >> 4, i = (k >> 2) & 3, j = k & 3;
        int h = clamp64(y + i - 1);
        int w = clamp64(x + j - 1);
        v = fsrc[((size_t)(bI * NC + c)) * 4096 + h * 64 + w];
    }
    __nv_bfloat16 hi = __float2bfloat16(v);
    __nv_bfloat16 lo = __float2bfloat16(v - __bfloat162float(hi));
    size_t base = ((size_t)bI * PPAD + p) * GK;
    d_Fbf[base + k]        = hi;
    d_Fbf[base + 1024 + k] = lo;
    d_Fbf[base + 2048 + k] = hi;
}

// ---------------------------------------------------------------------------
// 4/5) mask means
// ---------------------------------------------------------------------------
__global__ void mmk_kernel(const float* __restrict__ mask) {
    int idx = blockIdx.x * 256 + threadIdx.x;
    int l = idx & 1023, b = idx >> 10;
    int ly = l >> 5, lx = l & 31;
    const float* m = mask + (size_t)b * 4096;
    float s = 0.f;
    #pragma unroll
    for (int i = 0; i < 4; i++)
        #pragma unroll
        for (int j = 0; j < 4; j++)
            s += 1.0f - m[clamp64(2 * ly + i - 1) * 64 + clamp64(2 * lx + j - 1)];
    d_mmk[idx] = s * 0.0625f;
}
__global__ void mmp_kernel(const float* __restrict__ mask) {
    int p = blockIdx.x * 256 + threadIdx.x;
    if (p >= PP) return;
    int b = blockIdx.y;
    int y = p / 63, x = p - 63 * y;
    const float* m = mask + (size_t)b * 4096;
    float s = 0.f;
    #pragma unroll
    for (int i = 0; i < 4; i++)
        #pragma unroll
        for (int j = 0; j < 4; j++)
            s += 1.0f - m[clamp64(y + i - 1) * 64 + clamp64(x + j - 1)];
    d_mmp[b * PP + p] = s * 0.0625f;
}

// ---------------------------------------------------------------------------
// 6) HMMA GEMM: cos[b][m][n] = sum_k' Abf[b][m][k'] * Fbf[b][n][k']
//    128x128 tile, K chunks of 64, cp.async double buffer, mma.sync bf16
//    8 warps in 4(M)x2(N) grid; warp = 32M x 64N = 2 x 8 m16n8k16 tiles
// ---------------------------------------------------------------------------
__global__ void __launch_bounds__(256, 2)
gemm_hmma_kernel() {
    extern __shared__ char smem[];
    const uint32_t sb = smem_u32(smem);
    const int tid  = threadIdx.x;
    const int wid  = tid >> 5;
    const int lane = tid & 31;
    const int wm   = wid >> 1;        // 0..3
    const int wn   = wid & 1;         // 0..1
    const int bI = blockIdx.z;
    const int m0 = blockIdx.y * BM;
    const int n0 = blockIdx.x * BN;

    const char* Ag = (const char*)(d_Abf + (size_t)bI * LL * GK   + (size_t)m0 * GK);
    const char* Bg = (const char*)(d_Fbf + (size_t)bI * PPAD * GK + (size_t)n0 * GK);

    // loader indices: 1024 x 16B per tile, 4 (A) + 4 (B) per thread
    const int lr = tid >> 1;               // 0..127 row block base (2 cols per thread)
    const int lc = (tid & 1) * 4;          // 16B col base: 0 or 4

    float acc[2][8][4];
    #pragma unroll
    for (int mt = 0; mt < 2; mt++)
        #pragma unroll
        for (int nt = 0; nt < 8; nt++)
            #pragma unroll
            for (int e = 0; e < 4; e++) acc[mt][nt][e] = 0.f;

    // fragment lane addressing (constant over chunks)
    const int ar = wm * 32 + (lane & 15);          // + mt*16
    const int ac = (lane >> 4);                    // + ks*2
    const int br = wn * 64 + (lane & 7);           // + (2*pp + (lane>>4))*8
    const int bc = (lane >> 3) & 1;                // + ks*2
    const int bro = (lane >> 4) * 8;

    // ---- load helper (macro-ish lambda) ----
    auto load_chunk = [&](int ch, int buf) {
        const uint32_t ab = sb + buf * BUFBYTES;
        const uint32_t bb = ab + ABYTES;
        const size_t koff = (size_t)ch * (BKC * 2);
        #pragma unroll
        for (int i = 0; i < 4; i++) {
            int c = lc + i;
            cp_async16(swz(ab, lr, c), Ag + (size_t)lr * (GK * 2) + koff + c * 16);
        }
        #pragma unroll
        for (int i = 0; i < 4; i++) {
            int c = lc + i;
            cp_async16(swz(bb, lr, c), Bg + (size_t)lr * (GK * 2) + koff + c * 16);
        }
        asm volatile("cp.async.commit_group;" ::: "memory");
    };

    load_chunk(0, 0);
    load_chunk(1, 1);

    for (int ch = 0; ch < NCHUNK; ch++) {
        const int buf = ch & 1;
        if (ch == NCHUNK - 1) asm volatile("cp.async.wait_group 0;" ::: "memory");
        else                  asm volatile("cp.async.wait_group 1;" ::: "memory");
        __syncthreads();

        const uint32_t ab = sb + buf * BUFBYTES;
        const uint32_t bb = ab + ABYTES;
        #pragma unroll
        for (int ks = 0; ks < 4; ks++) {
            uint32_t afr[2][4];
            #pragma unroll
            for (int mt = 0; mt < 2; mt++)
                ldsm_x4(afr[mt], swz(ab, ar + mt * 16, ks * 2 + ac));
            uint32_t bfr[8][2];
            #pragma unroll
            for (int pp = 0; pp < 4; pp++) {
                uint32_t t[4];
                ldsm_x4(t, swz(bb, br + pp * 16 + bro, ks * 2 + bc));
                bfr[2 * pp][0] = t[0]; bfr[2 * pp][1] = t[1];
                bfr[2 * pp + 1][0] = t[2]; bfr[2 * pp + 1][1] = t[3];
            }
            #pragma unroll
            for (int mt = 0; mt < 2; mt++)
                #pragma unroll
                for (int nt = 0; nt < 8; nt++)
                    mma16816(acc[mt][nt], afr[mt], bfr[nt]);
        }
        __syncthreads();
        if (ch + 2 < NCHUNK) load_chunk(ch + 2, buf);
    }

    // epilogue: write fp32 to d_cos (row stride CSTR), guard n < PP
    #pragma unroll
    for (int mt = 0; mt < 2; mt++) {
        int mrow = m0 + wm * 32 + mt * 16 + (lane >> 2);
        float* C0 = d_cos + ((size_t)(bI * LL + mrow)) * CSTR;
        float* C1 = C0 + (size_t)8 * CSTR;
        #pragma unroll
        for (int nt = 0; nt < 8; nt++) {
            int n = n0 + wn * 64 + nt * 8 + 2 * (lane & 3);
            if (n + 1 < PP) {
                *(float2*)&C0[n] = make_float2(acc[mt][nt][0], acc[mt][nt][1]);
                *(float2*)&C1[n] = make_float2(acc[mt][nt][2], acc[mt][nt][3]);
            } else if (n < PP) {
                C0[n] = acc[mt][nt][0];
                C1[n] = acc[mt][nt][2];
            }
        }
    }
}

// ---------------------------------------------------------------------------
// 7) pass1: diag3 on flat (1024, 3969)
// ---------------------------------------------------------------------------
__global__ void pass1_kernel() {
    int q = blockIdx.x * 256 + threadIdx.x;
    if (q >= PP) return;
    int br = blockIdx.y;
    const float* base = d_cos + (size_t)(br >> 10) * LL * CSTR;
    int r = br & 1023;
    float s = base[(size_t)r * CSTR + q];
    if (r > 0 && q > 0)         s += base[(size_t)(r - 1) * CSTR + q - 1];
    if (r < 1023 && q < PP - 1) s += base[(size_t)(r + 1) * CSTR + q + 1];
    d_tmp[(size_t)br * CSTR + q] = s;
}

// ---------------------------------------------------------------------------
// 8) pass2: transposed-view diag3 + mask, back into d_cos
// ---------------------------------------------------------------------------
__global__ void pass2_kernel() {
    int q = blockIdx.x * 256 + threadIdx.x;
    if (q >= PP) return;
    int br = blockIdx.y;
    int b = br >> 10;
    int r = br & 1023;
    int ly = r >> 5, lx = r & 31;
    int r2 = lx * 32 + ly;
    int y = q / 63, x = q - 63 * y;
    int q2 = x * 63 + y;
    const float* tb = d_tmp + (size_t)b * LL * CSTR;
    float s = 0.f;
    #pragma unroll
    for (int d = -1; d <= 1; d++) {
        int rr = r2 + d, qq = q2 + d;
        if (rr >= 0 && rr < 1024 && qq >= 0 && qq < PP) {
            int lx2 = rr >> 5, ly2 = rr & 31;
            int x2 = qq / 63, y2 = qq - 63 * x2;
            s += tb[(size_t)(ly2 * 32 + lx2) * CSTR + (y2 * 63 + x2)];
        }
    }
    float mk = d_mmk[b * LL + r];
    float mp = d_mmp[b * PP + q];
    float mm = ((mk > mp && mp > 0.5f) || (mk == 1.0f)) ? 1.0f : 0.0f;
    d_cos[(size_t)br * CSTR + q] = s * mm;
}

// ---------------------------------------------------------------------------
// 9) softmax reduce over l
// ---------------------------------------------------------------------------
__global__ void smax_reduce_kernel() {
    int b  = blockIdx.y;
    int pl = threadIdx.x & 31;
    int lt = threadIdx.x >> 5;
    int p  = blockIdx.x * 32 + pl;
    float m = -1e30f, s = 0.f;
    if (p < PP) {
        const float* cf = d_cos + (size_t)b * LL * CSTR + p;
        for (int l = lt; l < LL; l += 8) {
            float x = 10.0f * cf[(size_t)l * CSTR];
            float mn = fmaxf(m, x);
            s = s * __expf(m - mn) + __expf(x - mn);
            m = mn;
        }
    }
    __shared__ float shm[8][32], shs[8][32];
    shm[lt][pl] = m;
    shs[lt][pl] = s;
    __syncthreads();
    if (lt == 0 && p < PP) {
        float M = shm[0][pl];
        #pragma unroll
        for (int t = 1; t < 8; t++) M = fmaxf(M, shm[t][pl]);
        float S = 0.f;
        #pragma unroll
        for (int t = 0; t < 8; t++) S += shs[t][pl] * __expf(shm[t][pl] - M);
        d_maxv[b * PP + p] = M;
        d_rcps[b * PP + p] = 1.0f / S;
    }
}

// ---------------------------------------------------------------------------
// 10) softmax write
// ---------------------------------------------------------------------------
__global__ void smax_write_kernel(float* __restrict__ out) {
    int q = blockIdx.x * 256 + threadIdx.x;
    if (q >= PP) return;
    int bl = blockIdx.y;
    int b = bl >> 10;
    float x = 10.0f * d_cos[(size_t)bl * CSTR + q];
    out[(size_t)bl * PP + q] = __expf(x - d_maxv[b * PP + q]) * d_rcps[b * PP + q];
}

// ---------------------------------------------------------------------------
extern "C" void kernel_launch(void* const* d_in, const int* in_sizes, int n_in,
                              void* d_out, int out_size) {
    const float* f    = (const float*)d_in[0];
    const float* bsrc = (const float*)d_in[1];
    const float* mask = (const float*)d_in[2];
    float* out = (float*)d_out;

    cudaFuncSetAttribute(gemm_hmma_kernel,
                         cudaFuncAttributeMaxDynamicSharedMemorySize, SM_BYTES);

    norm_kernel<<<NB * NC, 256>>>(bsrc);
    build_A_bf3<<<(NB * KK * LL) / 256, 256>>>(bsrc);
    build_F_bf3<<<(NB * PPAD * KK) / 256, 256>>>(f);
    mmk_kernel<<<(NB * LL) / 256, 256>>>(mask);
    mmp_kernel<<<dim3((PP + 255) / 256, NB), 256>>>(mask);

    gemm_hmma_kernel<<<dim3(PPAD / BN, LL / BM, NB), 256, SM_BYTES>>>();

    dim3 g2((PP + 255) / 256, NB * LL);
    pass1_kernel<<<g2, 256>>>();
    pass2_kernel<<<g2, 256>>>();

    smax_reduce_kernel<<<dim3((PP + 31) / 32, NB), 256>>>();
    smax_write_kernel<<<g2, 256>>>(out);
}

// round 8
// speedup vs baseline: 1.7476x; 1.1062x over previous
#include <cuda_runtime.h>
#include <cuda_bf16.h>
#include <cstdint>

// Problem constants
// B=4, C=64, H=W=64, PS=4, PD=1, UFSTRIDE=2, STRIDE=1, SCALE=10
// L = 1024 (M), hs=ws=63, P = 3969 (N, padded 4096), K = 1024 -> bf16 3-split K = 3072

#define NB    4
#define NC    64
#define LL    1024
#define KK    1024
#define GK    3072        // 3-split K
#define PP    3969
#define PPAD  4096
#define CSTR  3972

// GEMM tiling (HMMA mma.sync path — tcgen05 is ptxas-rejected: harness PTX targets sm_103)
#define BM    128
#define BN    256
#define BKC   64                    // bf16 per K-chunk (128 B rows)
#define NCHUNK (GK / BKC)           // 48
#define ABYTES (BM * 128)           // 16384
#define BBYTES (BN * 128)           // 32768
#define BUFBYTES (ABYTES + BBYTES)  // 49152
#define NSTAGE 3
#define SM_BYTES (NSTAGE * BUFBYTES) // 147456

static __device__ float d_invn[NB * NC];
static __device__ __align__(16) __nv_bfloat16 d_Abf[(size_t)NB * LL * GK];    // [b][l][k']
static __device__ __align__(16) __nv_bfloat16 d_Fbf[(size_t)NB * PPAD * GK];  // [b][p][k']
static __device__ float d_cos [(size_t)NB * LL * CSTR];
static __device__ float d_tmp [(size_t)NB * LL * CSTR];
static __device__ float d_mmk [NB * LL];
static __device__ float d_mmp [NB * PP];
static __device__ float d_maxv[NB * PP];
static __device__ float d_rcps[NB * PP];

__device__ __forceinline__ int clamp64(int v) { return min(max(v, 0), 63); }

__device__ __forceinline__ uint32_t smem_u32(const void* p) {
    uint32_t a;
    asm("{ .reg .u64 t; cvta.to.shared.u64 t, %1; cvt.u32.u64 %0, t; }" : "=r"(a) : "l"(p));
    return a;
}
__device__ __forceinline__ void cp_async16(uint32_t dst, const void* src) {
    asm volatile("cp.async.cg.shared.global [%0], [%1], 16;" :: "r"(dst), "l"(src) : "memory");
}
__device__ __forceinline__ void ldsm_x4(uint32_t* r, uint32_t addr) {
    asm volatile("ldmatrix.sync.aligned.m8n8.x4.shared.b16 {%0,%1,%2,%3}, [%4];"
                 : "=r"(r[0]), "=r"(r[1]), "=r"(r[2]), "=r"(r[3]) : "r"(addr));
}
__device__ __forceinline__ void mma16816(float* c, const uint32_t* a, const uint32_t* b) {
    asm volatile(
        "mma.sync.aligned.m16n8k16.row.col.f32.bf16.bf16.f32 "
        "{%0,%1,%2,%3}, {%4,%5,%6,%7}, {%8,%9}, {%0,%1,%2,%3};"
        : "+f"(c[0]), "+f"(c[1]), "+f"(c[2]), "+f"(c[3])
        : "r"(a[0]), "r"(a[1]), "r"(a[2]), "r"(a[3]), "r"(b[0]), "r"(b[1]));
}
// swizzled smem offset: row r (128 B), 16-byte column c
__device__ __forceinline__ uint32_t swz(uint32_t base, int r, int c) {
    return base + r * 128 + ((c ^ (r & 7)) << 4);
}

// ---------------------------------------------------------------------------
// 1) per-(b,c) inverse L2 norm of b
// ---------------------------------------------------------------------------
__global__ void norm_kernel(const float* __restrict__ bsrc) {
    int bc = blockIdx.x;
    const float* src = bsrc + (size_t)bc * 4096;
    float s = 0.f;
    for (int i = threadIdx.x; i < 4096; i += 256) {
        float v = src[i];
        s += v * v;
    }
    __shared__ float sh[256];
    sh[threadIdx.x] = s;
    __syncthreads();
    for (int o = 128; o > 0; o >>= 1) {
        if (threadIdx.x < o) sh[threadIdx.x] += sh[threadIdx.x + o];
        __syncthreads();
    }
    if (threadIdx.x == 0) d_invn[bc] = 1.0f / sqrtf(sh[0] + 1e-8f);
}

// ---------------------------------------------------------------------------
// 2) bf16-split kernel matrix A[b][l][k'] segs [hi, hi, lo]
// ---------------------------------------------------------------------------
__global__ void build_A_bf3(const float* __restrict__ bsrc) {
    int idx = blockIdx.x * 256 + threadIdx.x;
    int k  = idx & 1023;
    int l  = (idx >> 10) & 1023;
    int bI = idx >> 20;
    int c  = k >> 4, i = (k >> 2) & 3, j = k & 3;
    int ly = l >> 5, lx = l & 31;
    int h = clamp64(2 * ly + i - 1);
    int w = clamp64(2 * lx + j - 1);
    float a = bsrc[((size_t)(bI * NC + c)) * 4096 + h * 64 + w] * d_invn[bI * NC + c];
    __nv_bfloat16 hi = __float2bfloat16(a);
    __nv_bfloat16 lo = __float2bfloat16(a - __bfloat162float(hi));
    size_t base = ((size_t)(bI * LL + l)) * GK;
    d_Abf[base + k]        = hi;
    d_Abf[base + 1024 + k] = hi;
    d_Abf[base + 2048 + k] = lo;
}

// ---------------------------------------------------------------------------
// 3) bf16-split im2col F[b][p][k'] segs [hi, lo, hi]
// ---------------------------------------------------------------------------
__global__ void build_F_bf3(const float* __restrict__ fsrc) {
    int idx = blockIdx.x * 256 + threadIdx.x;
    int k  = idx & 1023;
    int p  = (idx >> 10) & 4095;
    int bI = idx >> 22;
    float v = 0.f;
    if (p < PP) {
        int y = p / 63, x = p - 63 * y;
        int c = k >> 4, i = (k >> 2) & 3, j = k & 3;
        int h = clamp64(y + i - 1);
        int w = clamp64(x + j - 1);
        v = fsrc[((size_t)(bI * NC + c)) * 4096 + h * 64 + w];
    }
    __nv_bfloat16 hi = __float2bfloat16(v);
    __nv_bfloat16 lo = __float2bfloat16(v - __bfloat162float(hi));
    size_t base = ((size_t)bI * PPAD + p) * GK;
    d_Fbf[base + k]        = hi;
    d_Fbf[base + 1024 + k] = lo;
    d_Fbf[base + 2048 + k] = hi;
}

// ---------------------------------------------------------------------------
// 4/5) mask means
// ---------------------------------------------------------------------------
__global__ void mmk_kernel(const float* __restrict__ mask) {
    int idx = blockIdx.x * 256 + threadIdx.x;
    int l = idx & 1023, b = idx >> 10;
    int ly = l >> 5, lx = l & 31;
    const float* m = mask + (size_t)b * 4096;
    float s = 0.f;
    #pragma unroll
    for (int i = 0; i < 4; i++)
        #pragma unroll
        for (int j = 0; j < 4; j++)
            s += 1.0f - m[clamp64(2 * ly + i - 1) * 64 + clamp64(2 * lx + j - 1)];
    d_mmk[idx] = s * 0.0625f;
}
__global__ void mmp_kernel(const float* __restrict__ mask) {
    int p = blockIdx.x * 256 + threadIdx.x;
    if (p >= PP) return;
    int b = blockIdx.y;
    int y = p / 63, x = p - 63 * y;
    const float* m = mask + (size_t)b * 4096;
    float s = 0.f;
    #pragma unroll
    for (int i = 0; i < 4; i++)
        #pragma unroll
        for (int j = 0; j < 4; j++)
            s += 1.0f - m[clamp64(y + i - 1) * 64 + clamp64(x + j - 1)];
    d_mmp[b * PP + p] = s * 0.0625f;
}

// ---------------------------------------------------------------------------
// 6) HMMA GEMM: cos[b][m][n] = sum_k' Abf[b][m][k'] * Fbf[b][n][k']
//    128x256 CTA tile, 3-stage cp.async pipeline, 8 warps in 2(M)x4(N) grid;
//    warp tile = 64M x 64N = 4 x 8 m16n8k16 -> 32 MMA : 8 LDSM.x4 per k16
// ---------------------------------------------------------------------------
__global__ void __launch_bounds__(256, 1)
gemm_hmma_kernel() {
    extern __shared__ char smem[];
    const uint32_t sb = smem_u32(smem);
    const int tid  = threadIdx.x;
    const int wid  = tid >> 5;
    const int lane = tid & 31;
    const int wm   = wid >> 2;        // 0..1
    const int wn   = wid & 3;         // 0..3
    const int bI = blockIdx.z;
    const int m0 = blockIdx.y * BM;
    const int n0 = blockIdx.x * BN;

    const char* Ag = (const char*)(d_Abf + (size_t)bI * LL * GK   + (size_t)m0 * GK);
    const char* Bg = (const char*)(d_Fbf + (size_t)bI * PPAD * GK + (size_t)n0 * GK);

    // loaders: A tile 1024 x 16B units, B tile 2048 x 16B units; 12 per thread
    float acc[4][8][4];
    #pragma unroll
    for (int mt = 0; mt < 4; mt++)
        #pragma unroll
        for (int nt = 0; nt < 8; nt++)
            #pragma unroll
            for (int e = 0; e < 4; e++) acc[mt][nt][e] = 0.f;

    // fragment lane addressing (constant over chunks)
    const int ar = wm * 64 + (lane & 15);          // + mt*16
    const int ac = (lane >> 4);                    // + ks*2
    const int br = wn * 64 + (lane & 7) + ((lane >> 4) << 3);  // + pp*16
    const int bc = (lane >> 3) & 1;                // + ks*2

    auto load_chunk = [&](int ch, int buf) {
        const uint32_t ab = sb + buf * BUFBYTES;
        const uint32_t bb = ab + ABYTES;
        const size_t koff = (size_t)ch * (BKC * 2);
        #pragma unroll
        for (int i = 0; i < 4; i++) {
            int idx = i * 256 + tid;
            int r = idx >> 3, c = idx & 7;
            cp_async16(swz(ab, r, c), Ag + (size_t)r * (GK * 2) + koff + c * 16);
        }
        #pragma unroll
        for (int i = 0; i < 8; i++) {
            int idx = i * 256 + tid;
            int r = idx >> 3, c = idx & 7;
            cp_async16(swz(bb, r, c), Bg + (size_t)r * (GK * 2) + koff + c * 16);
        }
        asm volatile("cp.async.commit_group;" ::: "memory");
    };

    load_chunk(0, 0);
    load_chunk(1, 1);
    load_chunk(2, 2);

    int buf = 0;
    for (int ch = 0; ch < NCHUNK; ch++) {
        if (ch < NCHUNK - 2)      asm volatile("cp.async.wait_group 2;" ::: "memory");
        else if (ch == NCHUNK - 2) asm volatile("cp.async.wait_group 1;" ::: "memory");
        else                      asm volatile("cp.async.wait_group 0;" ::: "memory");
        __syncthreads();

        const uint32_t ab = sb + buf * BUFBYTES;
        const uint32_t bb = ab + ABYTES;
        #pragma unroll
        for (int ks = 0; ks < 4; ks++) {
            uint32_t afr[4][4];
            #pragma unroll
            for (int mt = 0; mt < 4; mt++)
                ldsm_x4(afr[mt], swz(ab, ar + mt * 16, ks * 2 + ac));
            uint32_t bfr[8][2];
            #pragma unroll
            for (int pp = 0; pp < 4; pp++) {
                uint32_t t[4];
                ldsm_x4(t, swz(bb, br + pp * 16, ks * 2 + bc));
                bfr[2 * pp][0] = t[0]; bfr[2 * pp][1] = t[1];
                bfr[2 * pp + 1][0] = t[2]; bfr[2 * pp + 1][1] = t[3];
            }
            #pragma unroll
            for (int mt = 0; mt < 4; mt++)
                #pragma unroll
                for (int nt = 0; nt < 8; nt++)
                    mma16816(acc[mt][nt], afr[mt], bfr[nt]);
        }
        __syncthreads();
        if (ch + NSTAGE < NCHUNK) load_chunk(ch + NSTAGE, buf);
        buf = (buf == NSTAGE - 1) ? 0 : buf + 1;
    }

    // epilogue: write fp32 to d_cos (row stride CSTR), guard n < PP
    #pragma unroll
    for (int mt = 0; mt < 4; mt++) {
        int mrow = m0 + wm * 64 + mt * 16 + (lane >> 2);
        float* C0 = d_cos + ((size_t)(bI * LL + mrow)) * CSTR;
        float* C1 = C0 + (size_t)8 * CSTR;
        #pragma unroll
        for (int nt = 0; nt < 8; nt++) {
            int n = n0 + wn * 64 + nt * 8 + 2 * (lane & 3);
            if (n + 1 < PP) {
                *(float2*)&C0[n] = make_float2(acc[mt][nt][0], acc[mt][nt][1]);
                *(float2*)&C1[n] = make_float2(acc[mt][nt][2], acc[mt][nt][3]);
            } else if (n < PP) {
                C0[n] = acc[mt][nt][0];
                C1[n] = acc[mt][nt][2];
            }
        }
    }
}

// ---------------------------------------------------------------------------
// 7) pass1: diag3 on flat (1024, 3969)
// ---------------------------------------------------------------------------
__global__ void pass1_kernel() {
    int q = blockIdx.x * 256 + threadIdx.x;
    if (q >= PP) return;
    int br = blockIdx.y;
    const float* base = d_cos + (size_t)(br >> 10) * LL * CSTR;
    int r = br & 1023;
    float s = base[(size_t)r * CSTR + q];
    if (r > 0 && q > 0)         s += base[(size_t)(r - 1) * CSTR + q - 1];
    if (r < 1023 && q < PP - 1) s += base[(size_t)(r + 1) * CSTR + q + 1];
    d_tmp[(size_t)br * CSTR + q] = s;
}

// ---------------------------------------------------------------------------
// 8) pass2: transposed-view diag3 + mask, back into d_cos
// ---------------------------------------------------------------------------
__global__ void pass2_kernel() {
    int q = blockIdx.x * 256 + threadIdx.x;
    if (q >= PP) return;
    int br = blockIdx.y;
    int b = br >> 10;
    int r = br & 1023;
    int ly = r >> 5, lx = r & 31;
    int r2 = lx * 32 + ly;
    int y = q / 63, x = q - 63 * y;
    int q2 = x * 63 + y;
    const float* tb = d_tmp + (size_t)b * LL * CSTR;
    float s = 0.f;
    #pragma unroll
    for (int d = -1; d <= 1; d++) {
        int rr = r2 + d, qq = q2 + d;
        if (rr >= 0 && rr < 1024 && qq >= 0 && qq < PP) {
            int lx2 = rr >> 5, ly2 = rr & 31;
            int x2 = qq / 63, y2 = qq - 63 * x2;
            s += tb[(size_t)(ly2 * 32 + lx2) * CSTR + (y2 * 63 + x2)];
        }
    }
    float mk = d_mmk[b * LL + r];
    float mp = d_mmp[b * PP + q];
    float mm = ((mk > mp && mp > 0.5f) || (mk == 1.0f)) ? 1.0f : 0.0f;
    d_cos[(size_t)br * CSTR + q] = s * mm;
}

// ---------------------------------------------------------------------------
// 9) softmax reduce over l
// ---------------------------------------------------------------------------
__global__ void smax_reduce_kernel() {
    int b  = blockIdx.y;
    int pl = threadIdx.x & 31;
    int lt = threadIdx.x >> 5;
    int p  = blockIdx.x * 32 + pl;
    float m = -1e30f, s = 0.f;
    if (p < PP) {
        const float* cf = d_cos + (size_t)b * LL * CSTR + p;
        for (int l = lt; l < LL; l += 8) {
            float x = 10.0f * cf[(size_t)l * CSTR];
            float mn = fmaxf(m, x);
            s = s * __expf(m - mn) + __expf(x - mn);
            m = mn;
        }
    }
    __shared__ float shm[8][32], shs[8][32];
    shm[lt][pl] = m;
    shs[lt][pl] = s;
    __syncthreads();
    if (lt == 0 && p < PP) {
        float M = shm[0][pl];
        #pragma unroll
        for (int t = 1; t < 8; t++) M = fmaxf(M, shm[t][pl]);
        float S = 0.f;
        #pragma unroll
        for (int t = 0; t < 8; t++) S += shs[t][pl] * __expf(shm[t][pl] - M);
        d_maxv[b * PP + p] = M;
        d_rcps[b * PP + p] = 1.0f / S;
    }
}

// ---------------------------------------------------------------------------
// 10) softmax write
// ---------------------------------------------------------------------------
__global__ void smax_write_kernel(float* __restrict__ out) {
    int q = blockIdx.x * 256 + threadIdx.x;
    if (q >= PP) return;
    int bl = blockIdx.y;
    int b = bl >> 10;
    float x = 10.0f * d_cos[(size_t)bl * CSTR + q];
    out[(size_t)bl * PP + q] = __expf(x - d_maxv[b * PP + q]) * d_rcps[b * PP + q];
}

// ---------------------------------------------------------------------------
extern "C" void kernel_launch(void* const* d_in, const int* in_sizes, int n_in,
                              void* d_out, int out_size) {
    const float* f    = (const float*)d_in[0];
    const float* bsrc = (const float*)d_in[1];
    const float* mask = (const float*)d_in[2];
    float* out = (float*)d_out;

    cudaFuncSetAttribute(gemm_hmma_kernel,
                         cudaFuncAttributeMaxDynamicSharedMemorySize, SM_BYTES);

    norm_kernel<<<NB * NC, 256>>>(bsrc);
    build_A_bf3<<<(NB * KK * LL) / 256, 256>>>(bsrc);
    build_F_bf3<<<(NB * PPAD * KK) / 256, 256>>>(f);
    mmk_kernel<<<(NB * LL) / 256, 256>>>(mask);
    mmp_kernel<<<dim3((PP + 255) / 256, NB), 256>>>(mask);

    gemm_hmma_kernel<<<dim3(PPAD / BN, LL / BM, NB), 256, SM_BYTES>>>();

    dim3 g2((PP + 255) / 256, NB * LL);
    pass1_kernel<<<g2, 256>>>();
    pass2_kernel<<<g2, 256>>>();

    smax_reduce_kernel<<<dim3((PP + 31) / 32, NB), 256>>>();
    smax_write_kernel<<<g2, 256>>>(out);
}